// round 2
// baseline (speedup 1.0000x reference)
#include <cuda_runtime.h>
#include <cstdint>

// Problem constants
#define BATCH   16384
#define IN_SIZE 4096
#define NPART   8
#define DDIM    512

// Tiling
#define BM 128
#define BN 128
#define BK 16
#define THREADS 256

// Intermediate activation buffer (layer-1 output), device-global scratch
// (allocation APIs are forbidden; __device__ globals are the sanctioned path).
__device__ float g_mid[(size_t)BATCH * IN_SIZE];

__device__ __forceinline__ uint32_t f2tf32(float f) {
    uint32_t u;
    asm("cvt.rna.tf32.f32 %0, %1;" : "=r"(u) : "f"(f));
    return u;
}

__device__ __forceinline__ void mma_tf32(float c[4], const uint32_t a[4], const uint32_t b[2]) {
    asm volatile(
        "mma.sync.aligned.m16n8k8.row.col.f32.tf32.tf32.f32 "
        "{%0,%1,%2,%3}, {%4,%5,%6,%7}, {%8,%9}, {%0,%1,%2,%3};"
        : "+f"(c[0]), "+f"(c[1]), "+f"(c[2]), "+f"(c[3])
        : "r"(a[0]), "r"(a[1]), "r"(a[2]), "r"(a[3]),
          "r"(b[0]), "r"(b[1]));
}

// One layer: Out = swish( (A*gain + nb) @ W_p + bias, gamma, beta ) [+ residual]
// SECOND=false: A = X (kernel arg), writes g_mid
// SECOND=true : A = g_mid, residual = X, writes Out
template <bool SECOND>
__global__ __launch_bounds__(THREADS)
void bt_layer_kernel(const float* __restrict__ X,
                     const float* __restrict__ W,
                     const float* __restrict__ bias,
                     const float* __restrict__ gamma,
                     const float* __restrict__ beta,
                     const float* __restrict__ gain_p,
                     const float* __restrict__ nb_p,
                     float* __restrict__ Out) {
    const float* A   = SECOND ? g_mid : X;
    float*       out = SECOND ? Out   : g_mid;

    const int tid  = threadIdx.x;
    const int warp = tid >> 5;
    const int lane = tid & 31;

    const int mt = blockIdx.x;            // 0..127  (M tiles)
    const int ng = blockIdx.y;            // 0..31   (partition * 4 + n-tile)
    const int p  = ng >> 2;
    const int nt = ng & 3;

    const int row0  = mt * BM;            // global row base
    const int colp0 = nt * BN;            // column base within partition
    const int gcol0 = p * DDIM + colp0;   // global column base

    const float gain = gain_p[0];
    const float nb   = nb_p[0];

    // tf32 bits in smem; pads chosen for conflict-free fragment reads
    __shared__ uint32_t As[BM][BK + 4];    // stride 20 words
    __shared__ uint32_t Bs[BK][BN + 8];    // stride 136 words

    // Warp layout: 4 (M) x 2 (N); warp tile 32x64 -> 2 x 8 mma tiles (m16n8)
    const int wm = (warp >> 1) * 32;
    const int wn = (warp & 1) * 64;

    float acc[2][8][4];
    #pragma unroll
    for (int i = 0; i < 2; i++)
        #pragma unroll
        for (int j = 0; j < 8; j++)
            #pragma unroll
            for (int k = 0; k < 4; k++) acc[i][j][k] = 0.0f;

    const float* Wp = W + (size_t)p * DDIM * DDIM;

    for (int k0 = 0; k0 < DDIM; k0 += BK) {
        // ---- load A tile (128 x 16), with elementwise prologue, cvt->tf32
        #pragma unroll
        for (int i = 0; i < 2; i++) {
            int f  = tid + i * THREADS;        // float4 index 0..511
            int r  = f >> 2;                   // row 0..127
            int c4 = (f & 3) << 2;             // col 0,4,8,12
            const float4 v = *reinterpret_cast<const float4*>(
                &A[(size_t)(row0 + r) * IN_SIZE + p * DDIM + k0 + c4]);
            uint4 t;
            t.x = f2tf32(v.x * gain + nb);
            t.y = f2tf32(v.y * gain + nb);
            t.z = f2tf32(v.z * gain + nb);
            t.w = f2tf32(v.w * gain + nb);
            *reinterpret_cast<uint4*>(&As[r][c4]) = t;
        }
        // ---- load B tile (16 x 128), cvt->tf32
        #pragma unroll
        for (int i = 0; i < 2; i++) {
            int f  = tid + i * THREADS;        // float4 index 0..511
            int r  = f >> 5;                   // row 0..15
            int c4 = (f & 31) << 2;            // col 0..124 step 4
            const float4 v = *reinterpret_cast<const float4*>(
                &Wp[(size_t)(k0 + r) * DDIM + colp0 + c4]);
            uint4 t;
            t.x = f2tf32(v.x);
            t.y = f2tf32(v.y);
            t.z = f2tf32(v.z);
            t.w = f2tf32(v.w);
            *reinterpret_cast<uint4*>(&Bs[r][c4]) = t;
        }
        __syncthreads();

        // ---- compute: 2 k-steps of 8
        #pragma unroll
        for (int kk = 0; kk < BK; kk += 8) {
            uint32_t af[2][4];
            #pragma unroll
            for (int im = 0; im < 2; im++) {
                int r = wm + im * 16 + (lane >> 2);
                int c = kk + (lane & 3);
                af[im][0] = As[r][c];
                af[im][1] = As[r + 8][c];
                af[im][2] = As[r][c + 4];
                af[im][3] = As[r + 8][c + 4];
            }
            uint32_t bf[8][2];
            #pragma unroll
            for (int in_ = 0; in_ < 8; in_++) {
                int col = wn + in_ * 8 + (lane >> 2);
                int rk  = kk + (lane & 3);
                bf[in_][0] = Bs[rk][col];
                bf[in_][1] = Bs[rk + 4][col];
            }
            #pragma unroll
            for (int im = 0; im < 2; im++)
                #pragma unroll
                for (int in_ = 0; in_ < 8; in_++)
                    mma_tf32(acc[im][in_], af[im], bf[in_]);
        }
        __syncthreads();
    }

    // ---- epilogue: bias + parametric swish (+ residual), write out
    #pragma unroll
    for (int im = 0; im < 2; im++) {
        #pragma unroll
        for (int in_ = 0; in_ < 8; in_++) {
            const int r_lo = row0 + wm + im * 16 + (lane >> 2);
            const int c0   = gcol0 + wn + in_ * 8 + ((lane & 3) << 1);
            #pragma unroll
            for (int half = 0; half < 2; half++) {
                const int rg = r_lo + half * 8;
                #pragma unroll
                for (int cc = 0; cc < 2; cc++) {
                    const int cg = c0 + cc;
                    float v = acc[im][in_][half * 2 + cc] + bias[cg];
                    const float g  = gamma[cg];
                    const float bt = beta[cg];
                    const float sg = 1.0f / (1.0f + __expf(-bt * v));
                    float o = (g + sg * (1.0f - g)) * v;
                    if (SECOND) o += X[(size_t)rg * IN_SIZE + cg];
                    out[(size_t)rg * IN_SIZE + cg] = o;
                }
            }
        }
    }
}

extern "C" void kernel_launch(void* const* d_in, const int* in_sizes, int n_in,
                              void* d_out, int out_size) {
    (void)in_sizes; (void)n_in; (void)out_size;
    const float* x      = (const float*)d_in[0];
    const float* w1     = (const float*)d_in[1];
    const float* b1     = (const float*)d_in[2];
    const float* w2     = (const float*)d_in[3];
    const float* b2     = (const float*)d_in[4];
    const float* gamma1 = (const float*)d_in[5];
    const float* beta1  = (const float*)d_in[6];
    const float* gamma3 = (const float*)d_in[7];
    const float* beta3  = (const float*)d_in[8];
    const float* gain1  = (const float*)d_in[9];
    const float* nbias1 = (const float*)d_in[10];
    const float* gain3  = (const float*)d_in[11];
    const float* nbias3 = (const float*)d_in[12];
    float* out = (float*)d_out;

    dim3 grid(BATCH / BM, (NPART * DDIM) / BN);   // (128, 32)
    dim3 block(THREADS);

    // Layer 1: x -> g_mid
    bt_layer_kernel<false><<<grid, block>>>(x, w1, b1, gamma1, beta1,
                                            gain1, nbias1, out);
    // Layer 2: g_mid -> out (+x residual)
    bt_layer_kernel<true><<<grid, block>>>(x, w2, b2, gamma3, beta3,
                                           gain3, nbias3, out);
}